// round 1
// baseline (speedup 1.0000x reference)
#include <cuda_runtime.h>
#include <math.h>

#define NMAX 4096
#define TMAX 32   // NMAX/128

// Scratch (allocation-free rule: __device__ globals)
__device__ float d_buf[(size_t)NMAX * NMAX];     // pairwise distances, lower triangle tiles
__device__ float g_partials[TMAX * TMAX];        // per-tile distance sums
__device__ float g_coef[8];                      // -1/(bw*mult_f)
__device__ float g_sqn[NMAX];                    // row squared norms

// ---------------------------------------------------------------------------
// Kernel 1: row squared norms
// ---------------------------------------------------------------------------
__global__ void rownorm_kernel(const float* __restrict__ x, int K) {
    int row = blockIdx.x;
    const float* xr = x + (size_t)row * K;
    float s = 0.f;
    for (int k = threadIdx.x; k < K; k += 128) {
        float v = xr[k];
        s += v * v;
    }
    __shared__ float red[128];
    red[threadIdx.x] = s;
    __syncthreads();
    #pragma unroll
    for (int st = 64; st > 0; st >>= 1) {
        if (threadIdx.x < st) red[threadIdx.x] += red[threadIdx.x + st];
        __syncthreads();
    }
    if (threadIdx.x == 0) g_sqn[row] = red[0];
}

// ---------------------------------------------------------------------------
// Kernel 2: fused GEMM (X X^T) -> d = sqrt(max(sq_i+sq_j-2G,0)), lower triangle.
// 128x128 tile per block, BK=16, 256 threads, 8x8 per thread.
// Also produces per-tile sum of d (off-diagonal tiles weighted x2).
// ---------------------------------------------------------------------------
#define BM 128
#define BK 16

__global__ void __launch_bounds__(256, 2) gemm_d_kernel(
    const float* __restrict__ x, int N, int K)
{
    int bi = blockIdx.y, bj = blockIdx.x;
    int lin = bi * gridDim.x + bj;
    if (bj > bi) {                       // block-uniform early exit
        if (threadIdx.x == 0) g_partials[lin] = 0.f;
        return;
    }

    __shared__ float As[BK][BM + 4];     // pad to 132 -> conflict-free transposed stores
    __shared__ float Bs[BK][BM + 4];

    float acc[8][8];
    #pragma unroll
    for (int r = 0; r < 8; r++)
        #pragma unroll
        for (int c = 0; c < 8; c++) acc[r][c] = 0.f;

    int tid = threadIdx.x;
    int tx = tid & 15;        // column group
    int ty = tid >> 4;        // row group

    const float* Arow = x + (size_t)(bi * BM) * K;
    const float* Brow = x + (size_t)(bj * BM) * K;

    for (int kt = 0; kt < K; kt += BK) {
        // Load 128x16 tiles of A and B (transposed into [k][row])
        #pragma unroll
        for (int h = 0; h < 2; h++) {
            int f4  = tid + h * 256;          // 0..511 float4 slots
            int row = f4 >> 2;
            int c4  = (f4 & 3) * 4;
            float4 a = *(const float4*)(Arow + (size_t)row * K + kt + c4);
            float4 b = *(const float4*)(Brow + (size_t)row * K + kt + c4);
            As[c4 + 0][row] = a.x; As[c4 + 1][row] = a.y;
            As[c4 + 2][row] = a.z; As[c4 + 3][row] = a.w;
            Bs[c4 + 0][row] = b.x; Bs[c4 + 1][row] = b.y;
            Bs[c4 + 2][row] = b.z; Bs[c4 + 3][row] = b.w;
        }
        __syncthreads();

        #pragma unroll
        for (int k = 0; k < BK; k++) {
            float a[8], b[8];
            *(float4*)(a)     = *(const float4*)&As[k][ty * 8];
            *(float4*)(a + 4) = *(const float4*)&As[k][ty * 8 + 4];
            *(float4*)(b)     = *(const float4*)&Bs[k][tx * 8];
            *(float4*)(b + 4) = *(const float4*)&Bs[k][tx * 8 + 4];
            #pragma unroll
            for (int r = 0; r < 8; r++)
                #pragma unroll
                for (int c = 0; c < 8; c++)
                    acc[r][c] += a[r] * b[c];
        }
        __syncthreads();
    }

    // Epilogue: d = sqrt(max(sq_i + sq_j - 2G, 0)); store; local sum
    float lsum = 0.f;
    float sqj[8];
    #pragma unroll
    for (int c = 0; c < 8; c++) sqj[c] = g_sqn[bj * BM + tx * 8 + c];

    #pragma unroll
    for (int r = 0; r < 8; r++) {
        int gi = bi * BM + ty * 8 + r;
        float sqi = g_sqn[gi];
        #pragma unroll
        for (int c = 0; c < 8; c++) {
            float d2 = sqi + sqj[c] - 2.f * acc[r][c];
            float d  = sqrtf(fmaxf(d2, 0.f));
            acc[r][c] = d;
            lsum += d;
        }
        float4* p = (float4*)(d_buf + (size_t)gi * N + bj * BM + tx * 8);
        p[0] = make_float4(acc[r][0], acc[r][1], acc[r][2], acc[r][3]);
        p[1] = make_float4(acc[r][4], acc[r][5], acc[r][6], acc[r][7]);
    }

    // Deterministic block reduction of lsum (reuse As)
    __syncthreads();
    float* red = &As[0][0];
    red[tid] = lsum;
    __syncthreads();
    #pragma unroll
    for (int st = 128; st > 0; st >>= 1) {
        if (tid < st) red[tid] += red[tid + st];
        __syncthreads();
    }
    if (tid == 0) g_partials[lin] = red[0] * ((bi == bj) ? 1.f : 2.f);
}

// ---------------------------------------------------------------------------
// Kernel 3: reduce tile partials -> bandwidth -> exp coefficients
// ---------------------------------------------------------------------------
__global__ void reduce_kernel(const float* __restrict__ mult, int N, int F, int nTiles) {
    __shared__ float red[1024];
    int tid = threadIdx.x;
    red[tid] = (tid < nTiles) ? g_partials[tid] : 0.f;
    __syncthreads();
    #pragma unroll
    for (int st = 512; st > 0; st >>= 1) {
        if (tid < st) red[tid] += red[tid + st];
        __syncthreads();
    }
    if (tid < F && tid < 8) {
        float bw = red[0] / ((float)N * (float)(N - 1));
        g_coef[tid] = -1.f / (bw * mult[tid]);
    }
}

// ---------------------------------------------------------------------------
// Kernel 4: out[i,j] = sum_f exp(d * coef_f); lower-triangle tiles, shared
// staging for the mirrored write. F==5 fast path (the problem's F).
// ---------------------------------------------------------------------------
__global__ void __launch_bounds__(256) out_kernel(float* __restrict__ out, int N, int F) {
    int bi = blockIdx.y, bj = blockIdx.x;
    if (bj > bi) return;

    __shared__ float sm[128][65];   // [j][i0] for one 64-row half; stride 65 -> conflict-free
    int tid = threadIdx.x;

    float c0 = g_coef[0], c1 = g_coef[1], c2 = g_coef[2], c3 = g_coef[3], c4 = g_coef[4];
    bool fast5 = (F == 5);

    for (int h = 0; h < 2; h++) {
        // 64 rows x 128 cols = 2048 float4, 8 iters of 256 threads
        #pragma unroll
        for (int t = 0; t < 8; t++) {
            int idx4 = t * 256 + tid;
            int il   = h * 64 + (idx4 >> 5);      // local row within tile
            int jc   = (idx4 & 31) << 2;          // local col (x4)
            size_t off = (size_t)(bi * 128 + il) * N + bj * 128 + jc;
            float4 d4 = *(const float4*)(d_buf + off);
            float4 s4;
            if (fast5) {
                s4.x = __expf(d4.x * c0) + __expf(d4.x * c1) + __expf(d4.x * c2) + __expf(d4.x * c3) + __expf(d4.x * c4);
                s4.y = __expf(d4.y * c0) + __expf(d4.y * c1) + __expf(d4.y * c2) + __expf(d4.y * c3) + __expf(d4.y * c4);
                s4.z = __expf(d4.z * c0) + __expf(d4.z * c1) + __expf(d4.z * c2) + __expf(d4.z * c3) + __expf(d4.z * c4);
                s4.w = __expf(d4.w * c0) + __expf(d4.w * c1) + __expf(d4.w * c2) + __expf(d4.w * c3) + __expf(d4.w * c4);
            } else {
                s4.x = s4.y = s4.z = s4.w = 0.f;
                for (int f = 0; f < F; f++) {
                    float cf = g_coef[f];
                    s4.x += __expf(d4.x * cf);
                    s4.y += __expf(d4.y * cf);
                    s4.z += __expf(d4.z * cf);
                    s4.w += __expf(d4.w * cf);
                }
            }
            *(float4*)(out + off) = s4;
            int i0 = il - h * 64;
            sm[jc + 0][i0] = s4.x;
            sm[jc + 1][i0] = s4.y;
            sm[jc + 2][i0] = s4.z;
            sm[jc + 3][i0] = s4.w;
        }
        __syncthreads();
        if (bi != bj) {
            // mirror: 128 rows x 64 cols, coalesced
            #pragma unroll
            for (int t = 0; t < 32; t++) {
                int idx = t * 256 + tid;
                int jr  = idx >> 6;
                int i0  = idx & 63;
                out[(size_t)(bj * 128 + jr) * N + bi * 128 + h * 64 + i0] = sm[jr][i0];
            }
        }
        __syncthreads();
    }
}

// ---------------------------------------------------------------------------
extern "C" void kernel_launch(void* const* d_in, const int* in_sizes, int n_in,
                              void* d_out, int out_size) {
    const float* x    = (const float*)d_in[0];
    const float* mult = (const float*)d_in[1];
    float* out        = (float*)d_out;

    int N = (int)(sqrt((double)out_size) + 0.5);
    int K = in_sizes[0] / N;
    int F = in_sizes[1];
    int T = N / 128;

    rownorm_kernel<<<N, 128>>>(x, K);
    dim3 g(T, T);
    gemm_d_kernel<<<g, 256>>>(x, N, K);
    reduce_kernel<<<1, 1024>>>(mult, N, F, T * T);
    out_kernel<<<g, 256>>>(out, N, F);
}

// round 3
// speedup vs baseline: 3.3108x; 3.3108x over previous
#include <cuda_runtime.h>
#include <cuda_bf16.h>
#include <math.h>
#include <stdint.h>

#define NMAX 4096
#define KMAX 512
#define LTMAX 1024   // >= 32*33/2 = 528 triangular tiles

// ---- scratch (__device__ globals; allocation-free rule) ----
__device__ float          d_buf[(size_t)NMAX * NMAX];
__device__ __nv_bfloat16  g_xb[(size_t)NMAX * KMAX];
__device__ float          g_sqn[NMAX];
__device__ float          g_partials[LTMAX];
__device__ float          g_coef[8];
__device__ int            g_mode;

// ===========================================================================
// helpers (generic PTX only: ldmatrix / mma.sync bf16 / cp.async — all
// available on compute_103 virtual arch; NO tcgen05)
// ===========================================================================
__device__ __forceinline__ uint32_t smem_u32(const void* p) {
    uint32_t a;
    asm("{ .reg .u64 t; cvta.to.shared.u64 t, %1; cvt.u32.u64 %0, t; }"
        : "=r"(a) : "l"(p));
    return a;
}

#define CP_ASYNC16(saddr, gptr) \
    asm volatile("cp.async.cg.shared.global [%0], [%1], 16;" \
                 :: "r"(saddr), "l"((const void*)(gptr)) : "memory")
#define CP_COMMIT()  asm volatile("cp.async.commit_group;" ::: "memory")
#define CP_WAIT(n)   asm volatile("cp.async.wait_group %0;" :: "n"(n) : "memory")

#define LDSM_X4(r0, r1, r2, r3, addr) \
    asm volatile("ldmatrix.sync.aligned.m8n8.x4.shared.b16 {%0,%1,%2,%3}, [%4];" \
                 : "=r"(r0), "=r"(r1), "=r"(r2), "=r"(r3) : "r"(addr))

#define MMA_BF16(c, a, b) \
    asm volatile("mma.sync.aligned.m16n8k16.row.col.f32.bf16.bf16.f32 " \
                 "{%0,%1,%2,%3}, {%4,%5,%6,%7}, {%8,%9}, {%0,%1,%2,%3};" \
                 : "+f"((c)[0]), "+f"((c)[1]), "+f"((c)[2]), "+f"((c)[3]) \
                 : "r"((a)[0]), "r"((a)[1]), "r"((a)[2]), "r"((a)[3]), \
                   "r"((b)[0]), "r"((b)[1]))

// ===========================================================================
// Kernel 0: fp32 -> bf16
// ===========================================================================
__global__ void convert_kernel(const float* __restrict__ x, int total) {
    int i = (blockIdx.x * 256 + threadIdx.x) * 4;
    if (i >= total) return;
    float4 v = *(const float4*)(x + i);
    __nv_bfloat162 p0, p1;
    p0.x = __float2bfloat16(v.x); p0.y = __float2bfloat16(v.y);
    p1.x = __float2bfloat16(v.z); p1.y = __float2bfloat16(v.w);
    *(__nv_bfloat162*)(g_xb + i)     = p0;
    *(__nv_bfloat162*)(g_xb + i + 2) = p1;
}

// ===========================================================================
// Kernel 1: row squared norms from the SAME bf16 values (consistency with MMA)
// ===========================================================================
__global__ void rownorm_kernel(int K) {
    int row = blockIdx.x;
    const __nv_bfloat16* xr = g_xb + (size_t)row * K;
    float s = 0.f;
    for (int k = threadIdx.x * 2; k < K; k += 256) {
        __nv_bfloat162 v = *(const __nv_bfloat162*)(xr + k);
        float a = __bfloat162float(v.x), b = __bfloat162float(v.y);
        s += a * a + b * b;
    }
    __shared__ float red[128];
    red[threadIdx.x] = s;
    __syncthreads();
    #pragma unroll
    for (int st = 64; st > 0; st >>= 1) {
        if (threadIdx.x < st) red[threadIdx.x] += red[threadIdx.x + st];
        __syncthreads();
    }
    if (threadIdx.x == 0) g_sqn[row] = red[0];
}

// ===========================================================================
// Kernel 2: bf16 HMMA Gram tile -> d = sqrt(max(sq_i+sq_j-2G,0)), lower
// triangle (1D triangular grid). 256 threads, 128x128 tile, BK=64,
// cp.async double-buffered, 8 warps (4 M x 2 N), warp tile 32x64.
// ===========================================================================
#define SSTRIDE 72                        // bf16 units per smem row (144 B)
#define TILE_B  (128 * SSTRIDE * 2)       // 18432 B per operand tile
#define STAGE_B (2 * TILE_B)              // 36864 B per stage (A+B)
#define SMEM_BYTES (2 * STAGE_B)          // 73728 B

__global__ void __launch_bounds__(256, 2) gemm_kernel(int N, int K) {
    extern __shared__ char sm[];
    uint32_t smb = smem_u32(sm);

    int tid = threadIdx.x, lane = tid & 31, w = tid >> 5;
    int wy = w & 3, wx = w >> 2;          // warp: rows 32*wy, cols 64*wx

    // triangular decode
    int l = blockIdx.x;
    int bi = (int)((sqrtf(8.f * (float)l + 1.f) - 1.f) * 0.5f);
    while ((bi + 1) * (bi + 2) / 2 <= l) bi++;
    while (bi * (bi + 1) / 2 > l) bi--;
    int bj = l - bi * (bi + 1) / 2;

    const __nv_bfloat16* Ag = g_xb + (size_t)(bi * 128) * K;
    const __nv_bfloat16* Bg = g_xb + (size_t)(bj * 128) * K;

    float acc[2][8][4];
    #pragma unroll
    for (int mi = 0; mi < 2; mi++)
        #pragma unroll
        for (int ni = 0; ni < 8; ni++)
            #pragma unroll
            for (int q = 0; q < 4; q++) acc[mi][ni][q] = 0.f;

    // ldmatrix fragment base byte-offsets (within an operand tile)
    uint32_t a_off = ((wy * 32 + (lane & 15)) * SSTRIDE + (lane >> 4) * 8) * 2;
    uint32_t b_off = ((wx * 64 + (lane & 7) + ((lane >> 4) << 3)) * SSTRIDE
                      + ((lane >> 3) & 1) * 8) * 2;

    int nch = K / 64;

    // ---- stage loader: 128 rows x 64 bf16 per operand, 16B per cp.async ----
    #define LOAD_STAGE(st, kt) do {                                          \
        uint32_t sa_ = smb + (st) * STAGE_B;                                 \
        _Pragma("unroll")                                                    \
        for (int p_ = 0; p_ < 4; p_++) {                                     \
            int idx_ = tid + p_ * 256;                                       \
            int row_ = idx_ >> 3, c8_ = idx_ & 7;                            \
            uint32_t so_ = sa_ + row_ * (SSTRIDE * 2) + c8_ * 16;            \
            CP_ASYNC16(so_,          Ag + (size_t)row_ * K + (kt) + c8_ * 8);\
            CP_ASYNC16(so_ + TILE_B, Bg + (size_t)row_ * K + (kt) + c8_ * 8);\
        }                                                                    \
        CP_COMMIT();                                                         \
    } while (0)

    LOAD_STAGE(0, 0);

    for (int ch = 0; ch < nch; ch++) {
        if (ch + 1 < nch) {
            LOAD_STAGE((ch + 1) & 1, (ch + 1) * 64);
            CP_WAIT(1);
        } else {
            CP_WAIT(0);
        }
        __syncthreads();

        uint32_t sa = smb + (ch & 1) * STAGE_B;
        uint32_t sb = sa + TILE_B;
        #pragma unroll
        for (int kk = 0; kk < 4; kk++) {
            uint32_t a[2][4];
            #pragma unroll
            for (int mi = 0; mi < 2; mi++) {
                uint32_t ad = sa + a_off + (mi * 16 * SSTRIDE + kk * 16) * 2;
                LDSM_X4(a[mi][0], a[mi][1], a[mi][2], a[mi][3], ad);
            }
            uint32_t b[8][2];
            #pragma unroll
            for (int p = 0; p < 4; p++) {
                uint32_t bd = sb + b_off + (p * 16 * SSTRIDE + kk * 16) * 2;
                uint32_t r0, r1, r2, r3;
                LDSM_X4(r0, r1, r2, r3, bd);
                b[2 * p][0] = r0; b[2 * p][1] = r1;
                b[2 * p + 1][0] = r2; b[2 * p + 1][1] = r3;
            }
            #pragma unroll
            for (int mi = 0; mi < 2; mi++)
                #pragma unroll
                for (int ni = 0; ni < 8; ni++)
                    MMA_BF16(acc[mi][ni], a[mi], b[ni]);
        }
        __syncthreads();
    }

    // ---- epilogue: d = sqrt(max(sq_i + sq_j - 2G, 0)); diag forced to 0 ----
    int gRow = lane >> 2, cPair = (lane & 3) * 2;
    float lsum = 0.f;
    #pragma unroll
    for (int mi = 0; mi < 2; mi++) {
        int r0  = wy * 32 + mi * 16 + gRow;
        int gi0 = bi * 128 + r0;
        int gi1 = gi0 + 8;
        float sq0 = g_sqn[gi0], sq1 = g_sqn[gi1];
        #pragma unroll
        for (int ni = 0; ni < 8; ni++) {
            int gj = bj * 128 + wx * 64 + ni * 8 + cPair;
            float sqa = g_sqn[gj], sqb = g_sqn[gj + 1];
            float d00 = (gi0 == gj)     ? 0.f : sqrtf(fmaxf(sq0 + sqa - 2.f * acc[mi][ni][0], 0.f));
            float d01 = (gi0 == gj + 1) ? 0.f : sqrtf(fmaxf(sq0 + sqb - 2.f * acc[mi][ni][1], 0.f));
            float d10 = (gi1 == gj)     ? 0.f : sqrtf(fmaxf(sq1 + sqa - 2.f * acc[mi][ni][2], 0.f));
            float d11 = (gi1 == gj + 1) ? 0.f : sqrtf(fmaxf(sq1 + sqb - 2.f * acc[mi][ni][3], 0.f));
            lsum += d00 + d01 + d10 + d11;
            float2 v0; v0.x = d00; v0.y = d01;
            float2 v1; v1.x = d10; v1.y = d11;
            *(float2*)(d_buf + (size_t)gi0 * N + gj) = v0;
            *(float2*)(d_buf + (size_t)gi1 * N + gj) = v1;
        }
    }

    // deterministic block sum
    #pragma unroll
    for (int s = 16; s > 0; s >>= 1) lsum += __shfl_xor_sync(0xFFFFFFFFu, lsum, s);
    __shared__ float wsum[8];
    if (lane == 0) wsum[w] = lsum;
    __syncthreads();
    if (tid == 0) {
        float s = 0.f;
        #pragma unroll
        for (int i = 0; i < 8; i++) s += wsum[i];
        g_partials[l] = s * ((bi == bj) ? 1.f : 2.f);
    }
}

// ===========================================================================
// Kernel 3: reduce partials -> bandwidth -> exp coefficients (+mode detect)
// ===========================================================================
__global__ void reduce_kernel(const float* __restrict__ mult, int N, int F, int nTiles) {
    __shared__ float red[1024];
    int tid = threadIdx.x;
    float s = 0.f;
    for (int i = tid; i < nTiles; i += 1024) s += g_partials[i];
    red[tid] = s;
    __syncthreads();
    #pragma unroll
    for (int st = 512; st > 0; st >>= 1) {
        if (tid < st) red[tid] += red[tid + st];
        __syncthreads();
    }
    if (tid == 0) {
        float bw = red[0] / ((float)N * (float)(N - 1));
        bool geo = (F >= 1 && F <= 8);
        for (int f = 0; f + 1 < F; f++)
            if (fabsf(mult[f + 1] / mult[f] - 2.f) > 1e-3f) geo = false;
        g_mode = geo ? 1 : 0;
        for (int f = 0; f < F && f < 8; f++)
            g_coef[f] = -1.f / (bw * mult[f]);   // natural-log coefficients
    }
}

// ===========================================================================
// Kernel 4: out[i,j] = sum_f exp(d * coef_f). Geometric (ratio-2) fast path:
// u = exp(d*c_max); sum = u + u^2 + u^4 + ... (one MUFU + squarings).
// Triangular grid; mirror via SMEM transpose staging.
// ===========================================================================
__global__ void __launch_bounds__(256) out_kernel(float* __restrict__ out, int N, int F) {
    int l = blockIdx.x;
    int bi = (int)((sqrtf(8.f * (float)l + 1.f) - 1.f) * 0.5f);
    while ((bi + 1) * (bi + 2) / 2 <= l) bi++;
    while (bi * (bi + 1) / 2 > l) bi--;
    int bj = l - bi * (bi + 1) / 2;

    __shared__ float smt[128][65];
    int tid = threadIdx.x;
    int mode = g_mode;
    float cmax = g_coef[F - 1];

    for (int h = 0; h < 2; h++) {
        #pragma unroll 4
        for (int t = 0; t < 8; t++) {
            int idx4 = t * 256 + tid;
            int il = h * 64 + (idx4 >> 5);
            int jc = (idx4 & 31) << 2;
            size_t off = (size_t)(bi * 128 + il) * N + bj * 128 + jc;
            float4 d4 = *(const float4*)(d_buf + off);
            float4 s4;
            if (mode) {
                float u, v, a;
                u = __expf(d4.x * cmax); a = u; v = u;
                for (int k = 1; k < F; k++) { v *= v; a += v; } s4.x = a;
                u = __expf(d4.y * cmax); a = u; v = u;
                for (int k = 1; k < F; k++) { v *= v; a += v; } s4.y = a;
                u = __expf(d4.z * cmax); a = u; v = u;
                for (int k = 1; k < F; k++) { v *= v; a += v; } s4.z = a;
                u = __expf(d4.w * cmax); a = u; v = u;
                for (int k = 1; k < F; k++) { v *= v; a += v; } s4.w = a;
            } else {
                s4.x = s4.y = s4.z = s4.w = 0.f;
                for (int f = 0; f < F; f++) {
                    float cf = g_coef[f];
                    s4.x += __expf(d4.x * cf);
                    s4.y += __expf(d4.y * cf);
                    s4.z += __expf(d4.z * cf);
                    s4.w += __expf(d4.w * cf);
                }
            }
            *(float4*)(out + off) = s4;
            int i0 = il - h * 64;
            smt[jc + 0][i0] = s4.x;
            smt[jc + 1][i0] = s4.y;
            smt[jc + 2][i0] = s4.z;
            smt[jc + 3][i0] = s4.w;
        }
        __syncthreads();
        if (bi != bj) {
            #pragma unroll 8
            for (int t = 0; t < 32; t++) {
                int idx = t * 256 + tid;
                int jr = idx >> 6;
                int i0 = idx & 63;
                out[(size_t)(bj * 128 + jr) * N + bi * 128 + h * 64 + i0] = smt[jr][i0];
            }
        }
        __syncthreads();
    }
}

// ===========================================================================
extern "C" void kernel_launch(void* const* d_in, const int* in_sizes, int n_in,
                              void* d_out, int out_size) {
    const float* x    = (const float*)d_in[0];
    const float* mult = (const float*)d_in[1];
    float* out        = (float*)d_out;

    int N = (int)(sqrt((double)out_size) + 0.5);
    int K = in_sizes[0] / N;
    int F = in_sizes[1];
    int T = N / 128;
    int LT = T * (T + 1) / 2;

    cudaFuncSetAttribute(gemm_kernel,
                         cudaFuncAttributeMaxDynamicSharedMemorySize, SMEM_BYTES);

    int total = N * K;
    convert_kernel<<<(total / 4 + 255) / 256, 256>>>(x, total);
    rownorm_kernel<<<N, 128>>>(K);
    gemm_kernel<<<LT, 256, SMEM_BYTES>>>(N, K);
    reduce_kernel<<<1, 1024>>>(mult, N, F, LT);
    out_kernel<<<LT, 256>>>(out, N, F);
}